// round 8
// baseline (speedup 1.0000x reference)
#include <cuda_runtime.h>
#include <cstdint>

#define B_   4
#define S_   2048
#define D_   1024
#define H_   16
#define DK   64
#define MTOT (B_*S_)        // 8192
#define EPSV 1e-11f

// ---------------- scratch (device globals: no allocation allowed) ----------
__device__ float g_q[B_*H_*S_*DK];    // 32MB, head-major [bh][s][dk]
__device__ float g_k[B_*H_*S_*DK];
__device__ float g_v[B_*H_*S_*DK];
__device__ float g_ctx[MTOT*D_];      // [b][s][h*64+d]

// ---------------- f32x2 helpers (FFMA2: 2x fp32 throughput, exact fp32) ----
__device__ __forceinline__ unsigned long long pk2(float x, float y) {
    unsigned long long r;
    asm("mov.b64 %0, {%1, %2};" : "=l"(r) : "f"(x), "f"(y));
    return r;
}
__device__ __forceinline__ unsigned long long ffma2(unsigned long long a,
                                                    unsigned long long b,
                                                    unsigned long long c) {
    unsigned long long d;
    asm("fma.rn.f32x2 %0, %1, %2, %3;" : "=l"(d) : "l"(a), "l"(b), "l"(c));
    return d;
}
__device__ __forceinline__ unsigned long long fmul2(unsigned long long a,
                                                    unsigned long long b) {
    unsigned long long d;
    asm("mul.rn.f32x2 %0, %1, %2;" : "=l"(d) : "l"(a), "l"(b));
    return d;
}
__device__ __forceinline__ float2 upk2(unsigned long long v) {
    float2 r;
    asm("mov.b64 {%0, %1}, %2;" : "=f"(r.x), "=f"(r.y) : "l"(v));
    return r;
}

// ---------------- SGEMM: C = A(MxK) * W(NxK)^T + bias, M=8192,N=K=1024 -----
// 128x128 block, BK=8, 8x8 per thread (split-tile), FFMA2 inner loop.
// mode 0: C[m*N+n] (plain).  mode 1: head-major scatter for q/k/v.
__global__ __launch_bounds__(256, 2)
void sgemm_nt(const float* __restrict__ A, const float* __restrict__ W,
              const float* __restrict__ bias, float* __restrict__ C, int mode)
{
    __shared__ __align__(16) float As[8][128];
    __shared__ __align__(16) float Bs[8][128];

    const int tid  = threadIdx.x;
    const int bx   = blockIdx.x;       // n tile (0..7)
    const int by   = blockIdx.y;       // m tile (0..63)
    const int lrow = tid >> 1;         // 0..127
    const int lcol = (tid & 1) << 2;   // 0 or 4
    const float* Ag = A + (size_t)(by*128 + lrow)*D_ + lcol;
    const float* Wg = W + (size_t)(bx*128 + lrow)*D_ + lcol;

    const int ty = tid >> 4;           // 0..15
    const int tx = tid & 15;           // 0..15

    unsigned long long acc[8][4];
#pragma unroll
    for (int i = 0; i < 8; i++)
#pragma unroll
        for (int j = 0; j < 4; j++) acc[i][j] = 0ULL;

    float4 av = *(const float4*)(Ag);
    float4 bv = *(const float4*)(Wg);

    for (int kt = 0; kt < D_; kt += 8) {
        As[lcol+0][lrow] = av.x;
        As[lcol+1][lrow] = av.y;
        As[lcol+2][lrow] = av.z;
        As[lcol+3][lrow] = av.w;
        Bs[lcol+0][lrow] = bv.x;
        Bs[lcol+1][lrow] = bv.y;
        Bs[lcol+2][lrow] = bv.z;
        Bs[lcol+3][lrow] = bv.w;
        __syncthreads();

        if (kt + 8 < D_) {                       // prefetch next tile
            av = *(const float4*)(Ag + kt + 8);
            bv = *(const float4*)(Wg + kt + 8);
        }

#pragma unroll
        for (int k = 0; k < 8; k++) {
            float4 a0 = *(const float4*)&As[k][ty*4];
            float4 a1 = *(const float4*)&As[k][64 + ty*4];
            ulonglong2 b0 = *(const ulonglong2*)&Bs[k][tx*4];
            ulonglong2 b1 = *(const ulonglong2*)&Bs[k][64 + tx*4];
            float a[8] = {a0.x, a0.y, a0.z, a0.w, a1.x, a1.y, a1.z, a1.w};
            unsigned long long bb[4] = {b0.x, b0.y, b1.x, b1.y};
#pragma unroll
            for (int i = 0; i < 8; i++) {
                unsigned long long ad = pk2(a[i], a[i]);
#pragma unroll
                for (int j = 0; j < 4; j++)
                    acc[i][j] = ffma2(ad, bb[j], acc[i][j]);
            }
        }
        __syncthreads();
    }

#pragma unroll
    for (int i = 0; i < 8; i++) {
        int m = by*128 + ((i < 4) ? (ty*4 + i) : (64 + ty*4 + i - 4));
#pragma unroll
        for (int j = 0; j < 4; j++) {
            int n = bx*128 + ((j < 2) ? (tx*4 + j*2) : (64 + tx*4 + (j-2)*2));
            float2 v = upk2(acc[i][j]);
            float v0 = v.x + bias[n];
            float v1 = v.y + bias[n+1];
            if (mode == 0) {
                C[(size_t)m*D_ + n]     = v0;
                C[(size_t)m*D_ + n + 1] = v1;
            } else {
                // q/k/v scatter: [ (b*H+h) ][ s ][ d ]
                size_t base = ((size_t)((m >> 11)*H_ + (n >> 6)))*(size_t)(S_*DK)
                            + (size_t)(m & (S_-1))*DK;
                C[base + (n & 63)]       = v0;
                C[base + ((n+1) & 63)]   = v1;
            }
        }
    }
}

// ---------------- Flash attention, fp32, EPS-replace mask ------------------
#define BQ   64
#define CH   64
#define SPAD 68
#define ATTN_SMEM (4 * BQ * SPAD * (int)sizeof(float))   // 69632 B

union F4 { float4 v; float a[4]; };

__global__ __launch_bounds__(256, 2)
void attn_kernel(const float* __restrict__ Qm, const float* __restrict__ Km,
                 const float* __restrict__ Vm, const int* __restrict__ mask,
                 float* __restrict__ ctx)
{
    extern __shared__ __align__(16) float smbuf[];
    float (*Qs)[SPAD] = (float(*)[SPAD])(smbuf);
    float (*Ks)[SPAD] = (float(*)[SPAD])(smbuf + 1*BQ*SPAD);
    float (*Vs)[SPAD] = (float(*)[SPAD])(smbuf + 2*BQ*SPAD);
    float (*Ps)[SPAD] = (float(*)[SPAD])(smbuf + 3*BQ*SPAD);

    const int tid   = threadIdx.x;
    const int bh    = blockIdx.y;         // b*16 + h
    const int b     = bh >> 4;
    const int h     = bh & 15;
    const int qbase = blockIdx.x * BQ;

    const int ty = tid >> 4;              // 0..15 -> query rows ty*4..+3
    const int tx = tid & 15;              // 0..15
    const int r0 = ty * 4;
    const int d0 = tx * 4;                // head-dim cols in PV phase

    // load + pre-scale Q tile (scale = 1/sqrt(64) = 0.125)
    const float* Qg = Qm + ((size_t)bh*S_ + qbase)*DK;
    for (int idx = tid; idx < BQ*16; idx += 256) {
        int row = idx >> 4;
        int c4  = (idx & 15) << 2;
        float4 v = *(const float4*)(Qg + row*DK + c4);
        v.x *= 0.125f; v.y *= 0.125f; v.z *= 0.125f; v.w *= 0.125f;
        *(float4*)&Qs[row][c4] = v;
    }

    unsigned long long o2[4][2];          // O pairs along head dim
    float mi[4], li[4];
#pragma unroll
    for (int i = 0; i < 4; i++) {
        o2[i][0] = 0ULL; o2[i][1] = 0ULL;
        mi[i] = -1e30f;  li[i] = 0.f;
    }

    for (int kb = 0; kb < S_; kb += CH) {
        // load K/V chunk (Q sync covered by this barrier on first iter)
        const float* Kg = Km + ((size_t)bh*S_ + kb)*DK;
        const float* Vg = Vm + ((size_t)bh*S_ + kb)*DK;
        for (int idx = tid; idx < CH*16; idx += 256) {
            int row = idx >> 4;
            int c4  = (idx & 15) << 2;
            *(float4*)&Ks[row][c4] = *(const float4*)(Kg + row*DK + c4);
            *(float4*)&Vs[row][c4] = *(const float4*)(Vg + row*DK + c4);
        }
        __syncthreads();

        // ---- S = Q K^T : f32x2 horizontal accumulation along dk ----
        // thread owns rows r0..r0+3 and key cols {tx, tx+16, tx+32, tx+48}
        unsigned long long s2[4][4];
#pragma unroll
        for (int i = 0; i < 4; i++)
#pragma unroll
            for (int j = 0; j < 4; j++) s2[i][j] = 0ULL;

#pragma unroll 4
        for (int d = 0; d < DK; d += 4) {
            ulonglong2 qf[4], kf[4];
#pragma unroll
            for (int i = 0; i < 4; i++)
                qf[i] = *(const ulonglong2*)&Qs[r0+i][d];
#pragma unroll
            for (int j = 0; j < 4; j++)
                kf[j] = *(const ulonglong2*)&Ks[tx + 16*j][d];
#pragma unroll
            for (int i = 0; i < 4; i++)
#pragma unroll
                for (int j = 0; j < 4; j++) {
                    s2[i][j] = ffma2(qf[i].x, kf[j].x, s2[i][j]);
                    s2[i][j] = ffma2(qf[i].y, kf[j].y, s2[i][j]);
                }
        }

        // ---- mask + online softmax (row group = one half-warp) ----
#pragma unroll
        for (int i = 0; i < 4; i++) {
            const int* mrow = mask + ((size_t)b*S_ + (size_t)(qbase + r0 + i))*S_
                                   + kb + tx;
            float sv[4];
#pragma unroll
            for (int j = 0; j < 4; j++) {
                float2 u = upk2(s2[i][j]);
                float ss = u.x + u.y;
                sv[j] = (mrow[16*j] != 0) ? ss : EPSV;
            }
            float cm = fmaxf(fmaxf(sv[0], sv[1]), fmaxf(sv[2], sv[3]));
            cm = fmaxf(cm, __shfl_xor_sync(0xffffffffu, cm, 8, 16));
            cm = fmaxf(cm, __shfl_xor_sync(0xffffffffu, cm, 4, 16));
            cm = fmaxf(cm, __shfl_xor_sync(0xffffffffu, cm, 2, 16));
            cm = fmaxf(cm, __shfl_xor_sync(0xffffffffu, cm, 1, 16));
            float mnew  = fmaxf(mi[i], cm);
            float alpha = __expf(mi[i] - mnew);
            float psum  = 0.f;
#pragma unroll
            for (int j = 0; j < 4; j++) {
                float p = __expf(sv[j] - mnew);
                Ps[r0+i][tx + 16*j] = p;
                psum += p;
            }
            psum += __shfl_xor_sync(0xffffffffu, psum, 8, 16);
            psum += __shfl_xor_sync(0xffffffffu, psum, 4, 16);
            psum += __shfl_xor_sync(0xffffffffu, psum, 2, 16);
            psum += __shfl_xor_sync(0xffffffffu, psum, 1, 16);
            li[i] = li[i]*alpha + psum;
            mi[i] = mnew;
            unsigned long long a2 = pk2(alpha, alpha);
            o2[i][0] = fmul2(a2, o2[i][0]);
            o2[i][1] = fmul2(a2, o2[i][1]);
        }
        // P rows are produced & consumed by the same half-warp only
        __syncwarp();

        // ---- O += P @ V : pairs along head dim, natural V layout ----
#pragma unroll 4
        for (int c = 0; c < CH; c += 4) {
            F4 pf[4];
#pragma unroll
            for (int i = 0; i < 4; i++)
                pf[i].v = *(const float4*)&Ps[r0+i][c];
#pragma unroll
            for (int cc = 0; cc < 4; cc++) {
                ulonglong2 vv = *(const ulonglong2*)&Vs[c+cc][d0];
#pragma unroll
                for (int i = 0; i < 4; i++) {
                    unsigned long long pd = pk2(pf[i].a[cc], pf[i].a[cc]);
                    o2[i][0] = ffma2(pd, vv.x, o2[i][0]);
                    o2[i][1] = ffma2(pd, vv.y, o2[i][1]);
                }
            }
        }
        __syncthreads();   // all reads of Ks/Vs/Ps done before next chunk
    }

    // ---- normalize and write ctx[b][s][h*64+d] ----
#pragma unroll
    for (int i = 0; i < 4; i++) {
        int gq = qbase + r0 + i;
        float inv = 1.0f / li[i];
        float2 oa = upk2(o2[i][0]);
        float2 ob = upk2(o2[i][1]);
        float* dst = ctx + ((size_t)b*S_ + gq)*D_ + h*DK + d0;
        dst[0] = oa.x * inv;
        dst[1] = oa.y * inv;
        dst[2] = ob.x * inv;
        dst[3] = ob.y * inv;
    }
}

// ---------------- launch ---------------------------------------------------
extern "C" void kernel_launch(void* const* d_in, const int* in_sizes, int n_in,
                              void* d_out, int out_size)
{
    const float* query = (const float*)d_in[0];
    const float* key_  = (const float*)d_in[1];
    const float* value = (const float*)d_in[2];
    const int*   mask  = (const int*)  d_in[3];
    const float* wq    = (const float*)d_in[4];
    const float* bq    = (const float*)d_in[5];
    const float* wk    = (const float*)d_in[6];
    const float* bk    = (const float*)d_in[7];
    const float* wv    = (const float*)d_in[8];
    const float* bv    = (const float*)d_in[9];
    const float* wo    = (const float*)d_in[10];
    const float* bo    = (const float*)d_in[11];
    float* out = (float*)d_out;

    float *qp, *kp, *vp, *cp;
    cudaGetSymbolAddress((void**)&qp, g_q);
    cudaGetSymbolAddress((void**)&kp, g_k);
    cudaGetSymbolAddress((void**)&vp, g_v);
    cudaGetSymbolAddress((void**)&cp, g_ctx);

    // >48KB dynamic smem for attention (idempotent; also set on the
    // non-captured correctness call, so capture-time behavior is safe)
    cudaFuncSetAttribute(attn_kernel,
                         cudaFuncAttributeMaxDynamicSharedMemorySize,
                         ATTN_SMEM);

    dim3 blk(256);
    dim3 gg(D_/128, MTOT/128);          // (8, 64)

    sgemm_nt<<<gg, blk>>>(query, wq, bq, qp, 1);
    sgemm_nt<<<gg, blk>>>(key_,  wk, bk, kp, 1);
    sgemm_nt<<<gg, blk>>>(value, wv, bv, vp, 1);

    attn_kernel<<<dim3(S_/BQ, B_*H_), blk, ATTN_SMEM>>>(qp, kp, vp, mask, cp);

    sgemm_nt<<<gg, blk>>>(cp, wo, bo, out, 0);
}

// round 9
// speedup vs baseline: 1.0019x; 1.0019x over previous
#include <cuda_runtime.h>
#include <cstdint>

#define B_   4
#define S_   2048
#define D_   1024
#define H_   16
#define DK   64
#define MTOT (B_*S_)        // 8192
#define EPSV 1e-11f

// ---------------- scratch (device globals: no allocation allowed) ----------
__device__ float g_q[B_*H_*S_*DK];    // 32MB, head-major [bh][s][dk]
__device__ float g_k[B_*H_*S_*DK];
__device__ float g_v[B_*H_*S_*DK];
__device__ float g_ctx[MTOT*D_];      // [b][s][h*64+d]

// ---------------- f32x2 helpers (FFMA2: 2x fp32 throughput, exact fp32) ----
__device__ __forceinline__ unsigned long long pk2(float x, float y) {
    unsigned long long r;
    asm("mov.b64 %0, {%1, %2};" : "=l"(r) : "f"(x), "f"(y));
    return r;
}
__device__ __forceinline__ unsigned long long ffma2(unsigned long long a,
                                                    unsigned long long b,
                                                    unsigned long long c) {
    unsigned long long d;
    asm("fma.rn.f32x2 %0, %1, %2, %3;" : "=l"(d) : "l"(a), "l"(b), "l"(c));
    return d;
}
__device__ __forceinline__ unsigned long long fmul2(unsigned long long a,
                                                    unsigned long long b) {
    unsigned long long d;
    asm("mul.rn.f32x2 %0, %1, %2;" : "=l"(d) : "l"(a), "l"(b));
    return d;
}
__device__ __forceinline__ float2 upk2(unsigned long long v) {
    float2 r;
    asm("mov.b64 {%0, %1}, %2;" : "=f"(r.x), "=f"(r.y) : "l"(v));
    return r;
}

// ---------------- SGEMM: C = A(MxK) * W(NxK)^T + bias, M=8192,N=K=1024 -----
// 128x128 block, BK=8, 8x8 per thread (split-tile), FFMA2 inner loop.
// mode 0: C[m*N+n] (plain).  mode 1: head-major scatter for q/k/v.
__global__ __launch_bounds__(256, 2)
void sgemm_nt(const float* __restrict__ A, const float* __restrict__ W,
              const float* __restrict__ bias, float* __restrict__ C, int mode)
{
    __shared__ __align__(16) float As[8][128];
    __shared__ __align__(16) float Bs[8][128];

    const int tid  = threadIdx.x;
    const int bx   = blockIdx.x;       // n tile (0..7)
    const int by   = blockIdx.y;       // m tile (0..63)
    const int lrow = tid >> 1;         // 0..127
    const int lcol = (tid & 1) << 2;   // 0 or 4
    const float* Ag = A + (size_t)(by*128 + lrow)*D_ + lcol;
    const float* Wg = W + (size_t)(bx*128 + lrow)*D_ + lcol;

    const int ty = tid >> 4;           // 0..15
    const int tx = tid & 15;           // 0..15

    unsigned long long acc[8][4];
#pragma unroll
    for (int i = 0; i < 8; i++)
#pragma unroll
        for (int j = 0; j < 4; j++) acc[i][j] = 0ULL;

    float4 av = *(const float4*)(Ag);
    float4 bv = *(const float4*)(Wg);

    for (int kt = 0; kt < D_; kt += 8) {
        As[lcol+0][lrow] = av.x;
        As[lcol+1][lrow] = av.y;
        As[lcol+2][lrow] = av.z;
        As[lcol+3][lrow] = av.w;
        Bs[lcol+0][lrow] = bv.x;
        Bs[lcol+1][lrow] = bv.y;
        Bs[lcol+2][lrow] = bv.z;
        Bs[lcol+3][lrow] = bv.w;
        __syncthreads();

        if (kt + 8 < D_) {                       // prefetch next tile
            av = *(const float4*)(Ag + kt + 8);
            bv = *(const float4*)(Wg + kt + 8);
        }

#pragma unroll
        for (int k = 0; k < 8; k++) {
            float4 a0 = *(const float4*)&As[k][ty*4];
            float4 a1 = *(const float4*)&As[k][64 + ty*4];
            ulonglong2 b0 = *(const ulonglong2*)&Bs[k][tx*4];
            ulonglong2 b1 = *(const ulonglong2*)&Bs[k][64 + tx*4];
            float a[8] = {a0.x, a0.y, a0.z, a0.w, a1.x, a1.y, a1.z, a1.w};
            unsigned long long bb[4] = {b0.x, b0.y, b1.x, b1.y};
#pragma unroll
            for (int i = 0; i < 8; i++) {
                unsigned long long ad = pk2(a[i], a[i]);
#pragma unroll
                for (int j = 0; j < 4; j++)
                    acc[i][j] = ffma2(ad, bb[j], acc[i][j]);
            }
        }
        __syncthreads();
    }

#pragma unroll
    for (int i = 0; i < 8; i++) {
        int m = by*128 + ((i < 4) ? (ty*4 + i) : (64 + ty*4 + i - 4));
#pragma unroll
        for (int j = 0; j < 4; j++) {
            int n = bx*128 + ((j < 2) ? (tx*4 + j*2) : (64 + tx*4 + (j-2)*2));
            float2 v = upk2(acc[i][j]);
            float v0 = v.x + bias[n];
            float v1 = v.y + bias[n+1];
            if (mode == 0) {
                C[(size_t)m*D_ + n]     = v0;
                C[(size_t)m*D_ + n + 1] = v1;
            } else {
                // q/k/v scatter: [ (b*H+h) ][ s ][ d ]
                size_t base = ((size_t)((m >> 11)*H_ + (n >> 6)))*(size_t)(S_*DK)
                            + (size_t)(m & (S_-1))*DK;
                C[base + (n & 63)]       = v0;
                C[base + ((n+1) & 63)]   = v1;
            }
        }
    }
}

// ---------------- Flash attention, fp32, EPS-replace mask ------------------
#define BQ   64
#define CH   64
#define SPAD 68
#define ATTN_SMEM (4 * BQ * SPAD * (int)sizeof(float))   // 69632 B

union F4 { float4 v; float a[4]; };

__global__ __launch_bounds__(256, 2)
void attn_kernel(const float* __restrict__ Qm, const float* __restrict__ Km,
                 const float* __restrict__ Vm, const int* __restrict__ mask,
                 float* __restrict__ ctx)
{
    extern __shared__ __align__(16) float smbuf[];
    float (*Qs)[SPAD] = (float(*)[SPAD])(smbuf);
    float (*Ks)[SPAD] = (float(*)[SPAD])(smbuf + 1*BQ*SPAD);
    float (*Vs)[SPAD] = (float(*)[SPAD])(smbuf + 2*BQ*SPAD);
    float (*Ps)[SPAD] = (float(*)[SPAD])(smbuf + 3*BQ*SPAD);

    const int tid   = threadIdx.x;
    const int bh    = blockIdx.y;         // b*16 + h
    const int b     = bh >> 4;
    const int h     = bh & 15;
    const int qbase = blockIdx.x * BQ;

    const int ty = tid >> 4;              // 0..15 -> query rows ty*4..+3
    const int tx = tid & 15;              // 0..15
    const int r0 = ty * 4;
    const int d0 = tx * 4;                // head-dim cols in PV phase

    // load + pre-scale Q tile (scale = 1/sqrt(64) = 0.125)
    const float* Qg = Qm + ((size_t)bh*S_ + qbase)*DK;
    for (int idx = tid; idx < BQ*16; idx += 256) {
        int row = idx >> 4;
        int c4  = (idx & 15) << 2;
        float4 v = *(const float4*)(Qg + row*DK + c4);
        v.x *= 0.125f; v.y *= 0.125f; v.z *= 0.125f; v.w *= 0.125f;
        *(float4*)&Qs[row][c4] = v;
    }

    unsigned long long o2[4][2];          // O pairs along head dim
    float mi[4], li[4];
#pragma unroll
    for (int i = 0; i < 4; i++) {
        o2[i][0] = 0ULL; o2[i][1] = 0ULL;
        mi[i] = -1e30f;  li[i] = 0.f;
    }

    for (int kb = 0; kb < S_; kb += CH) {
        // load K/V chunk (Q sync covered by this barrier on first iter)
        const float* Kg = Km + ((size_t)bh*S_ + kb)*DK;
        const float* Vg = Vm + ((size_t)bh*S_ + kb)*DK;
        for (int idx = tid; idx < CH*16; idx += 256) {
            int row = idx >> 4;
            int c4  = (idx & 15) << 2;
            *(float4*)&Ks[row][c4] = *(const float4*)(Kg + row*DK + c4);
            *(float4*)&Vs[row][c4] = *(const float4*)(Vg + row*DK + c4);
        }
        __syncthreads();

        // ---- S = Q K^T : f32x2 horizontal accumulation along dk ----
        // thread owns rows r0..r0+3 and key cols {tx, tx+16, tx+32, tx+48}
        unsigned long long s2[4][4];
#pragma unroll
        for (int i = 0; i < 4; i++)
#pragma unroll
            for (int j = 0; j < 4; j++) s2[i][j] = 0ULL;

#pragma unroll 4
        for (int d = 0; d < DK; d += 4) {
            ulonglong2 qf[4], kf[4];
#pragma unroll
            for (int i = 0; i < 4; i++)
                qf[i] = *(const ulonglong2*)&Qs[r0+i][d];
#pragma unroll
            for (int j = 0; j < 4; j++)
                kf[j] = *(const ulonglong2*)&Ks[tx + 16*j][d];
#pragma unroll
            for (int i = 0; i < 4; i++)
#pragma unroll
                for (int j = 0; j < 4; j++) {
                    s2[i][j] = ffma2(qf[i].x, kf[j].x, s2[i][j]);
                    s2[i][j] = ffma2(qf[i].y, kf[j].y, s2[i][j]);
                }
        }

        // ---- mask + online softmax (row group = one half-warp) ----
#pragma unroll
        for (int i = 0; i < 4; i++) {
            const int* mrow = mask + ((size_t)b*S_ + (size_t)(qbase + r0 + i))*S_
                                   + kb + tx;
            float sv[4];
#pragma unroll
            for (int j = 0; j < 4; j++) {
                float2 u = upk2(s2[i][j]);
                float ss = u.x + u.y;
                sv[j] = (mrow[16*j] != 0) ? ss : EPSV;
            }
            float cm = fmaxf(fmaxf(sv[0], sv[1]), fmaxf(sv[2], sv[3]));
            cm = fmaxf(cm, __shfl_xor_sync(0xffffffffu, cm, 8, 16));
            cm = fmaxf(cm, __shfl_xor_sync(0xffffffffu, cm, 4, 16));
            cm = fmaxf(cm, __shfl_xor_sync(0xffffffffu, cm, 2, 16));
            cm = fmaxf(cm, __shfl_xor_sync(0xffffffffu, cm, 1, 16));
            float mnew  = fmaxf(mi[i], cm);
            float alpha = __expf(mi[i] - mnew);
            float psum  = 0.f;
#pragma unroll
            for (int j = 0; j < 4; j++) {
                float p = __expf(sv[j] - mnew);
                Ps[r0+i][tx + 16*j] = p;
                psum += p;
            }
            psum += __shfl_xor_sync(0xffffffffu, psum, 8, 16);
            psum += __shfl_xor_sync(0xffffffffu, psum, 4, 16);
            psum += __shfl_xor_sync(0xffffffffu, psum, 2, 16);
            psum += __shfl_xor_sync(0xffffffffu, psum, 1, 16);
            li[i] = li[i]*alpha + psum;
            mi[i] = mnew;
            unsigned long long a2 = pk2(alpha, alpha);
            o2[i][0] = fmul2(a2, o2[i][0]);
            o2[i][1] = fmul2(a2, o2[i][1]);
        }
        // P rows are produced & consumed by the same half-warp only
        __syncwarp();

        // ---- O += P @ V : pairs along head dim, natural V layout ----
#pragma unroll 4
        for (int c = 0; c < CH; c += 4) {
            F4 pf[4];
#pragma unroll
            for (int i = 0; i < 4; i++)
                pf[i].v = *(const float4*)&Ps[r0+i][c];
#pragma unroll
            for (int cc = 0; cc < 4; cc++) {
                ulonglong2 vv = *(const ulonglong2*)&Vs[c+cc][d0];
#pragma unroll
                for (int i = 0; i < 4; i++) {
                    unsigned long long pd = pk2(pf[i].a[cc], pf[i].a[cc]);
                    o2[i][0] = ffma2(pd, vv.x, o2[i][0]);
                    o2[i][1] = ffma2(pd, vv.y, o2[i][1]);
                }
            }
        }
        __syncthreads();   // all reads of Ks/Vs/Ps done before next chunk
    }

    // ---- normalize and write ctx[b][s][h*64+d] ----
#pragma unroll
    for (int i = 0; i < 4; i++) {
        int gq = qbase + r0 + i;
        float inv = 1.0f / li[i];
        float2 oa = upk2(o2[i][0]);
        float2 ob = upk2(o2[i][1]);
        float* dst = ctx + ((size_t)b*S_ + gq)*D_ + h*DK + d0;
        dst[0] = oa.x * inv;
        dst[1] = oa.y * inv;
        dst[2] = ob.x * inv;
        dst[3] = ob.y * inv;
    }
}

// ---------------- launch ---------------------------------------------------
extern "C" void kernel_launch(void* const* d_in, const int* in_sizes, int n_in,
                              void* d_out, int out_size)
{
    const float* query = (const float*)d_in[0];
    const float* key_  = (const float*)d_in[1];
    const float* value = (const float*)d_in[2];
    const int*   mask  = (const int*)  d_in[3];
    const float* wq    = (const float*)d_in[4];
    const float* bq    = (const float*)d_in[5];
    const float* wk    = (const float*)d_in[6];
    const float* bk    = (const float*)d_in[7];
    const float* wv    = (const float*)d_in[8];
    const float* bv    = (const float*)d_in[9];
    const float* wo    = (const float*)d_in[10];
    const float* bo    = (const float*)d_in[11];
    float* out = (float*)d_out;

    float *qp, *kp, *vp, *cp;
    cudaGetSymbolAddress((void**)&qp, g_q);
    cudaGetSymbolAddress((void**)&kp, g_k);
    cudaGetSymbolAddress((void**)&vp, g_v);
    cudaGetSymbolAddress((void**)&cp, g_ctx);

    // >48KB dynamic smem for attention (idempotent; also set on the
    // non-captured correctness call, so capture-time behavior is safe)
    cudaFuncSetAttribute(attn_kernel,
                         cudaFuncAttributeMaxDynamicSharedMemorySize,
                         ATTN_SMEM);

    dim3 blk(256);
    dim3 gg(D_/128, MTOT/128);          // (8, 64)

    sgemm_nt<<<gg, blk>>>(query, wq, bq, qp, 1);
    sgemm_nt<<<gg, blk>>>(key_,  wk, bk, kp, 1);
    sgemm_nt<<<gg, blk>>>(value, wv, bv, vp, 1);

    attn_kernel<<<dim3(S_/BQ, B_*H_), blk, ATTN_SMEM>>>(qp, kp, vp, mask, cp);

    sgemm_nt<<<gg, blk>>>(cp, wo, bo, out, 0);
}

// round 11
// speedup vs baseline: 1.0021x; 1.0001x over previous
#include <cuda_runtime.h>
#include <cstdint>

#define B_   4
#define S_   2048
#define D_   1024
#define H_   16
#define DK   64
#define MTOT (B_*S_)        // 8192
#define EPSV 1e-11f

// ---------------- scratch (device globals: no allocation allowed) ----------
__device__ float g_q[B_*H_*S_*DK];    // 32MB, head-major [bh][s][dk]
__device__ float g_k[B_*H_*S_*DK];
__device__ float g_v[B_*H_*S_*DK];
__device__ float g_ctx[MTOT*D_];      // [b][s][h*64+d]

// ---------------- f32x2 helpers (FFMA2: 2x fp32 throughput, exact fp32) ----
__device__ __forceinline__ unsigned long long pk2(float x, float y) {
    unsigned long long r;
    asm("mov.b64 %0, {%1, %2};" : "=l"(r) : "f"(x), "f"(y));
    return r;
}
__device__ __forceinline__ unsigned long long ffma2(unsigned long long a,
                                                    unsigned long long b,
                                                    unsigned long long c) {
    unsigned long long d;
    asm("fma.rn.f32x2 %0, %1, %2, %3;" : "=l"(d) : "l"(a), "l"(b), "l"(c));
    return d;
}
__device__ __forceinline__ unsigned long long fmul2(unsigned long long a,
                                                    unsigned long long b) {
    unsigned long long d;
    asm("mul.rn.f32x2 %0, %1, %2;" : "=l"(d) : "l"(a), "l"(b));
    return d;
}
__device__ __forceinline__ float2 upk2(unsigned long long v) {
    float2 r;
    asm("mov.b64 {%0, %1}, %2;" : "=f"(r.x), "=f"(r.y) : "l"(v));
    return r;
}

// ---------------- SGEMM: C = A(MxK) * W(NxK)^T + bias, M=8192,N=K=1024 -----
// 128x128 block, BK=8, 8x8 per thread (split-tile), FFMA2 inner loop.
// mode 0: C[m*N+n] (plain).  mode 1: head-major scatter for q/k/v.
__global__ __launch_bounds__(256, 2)
void sgemm_nt(const float* __restrict__ A, const float* __restrict__ W,
              const float* __restrict__ bias, float* __restrict__ C, int mode)
{
    __shared__ __align__(16) float As[8][128];
    __shared__ __align__(16) float Bs[8][128];

    const int tid  = threadIdx.x;
    const int bx   = blockIdx.x;       // n tile (0..7)
    const int by   = blockIdx.y;       // m tile (0..63)
    const int lrow = tid >> 1;         // 0..127
    const int lcol = (tid & 1) << 2;   // 0 or 4
    const float* Ag = A + (size_t)(by*128 + lrow)*D_ + lcol;
    const float* Wg = W + (size_t)(bx*128 + lrow)*D_ + lcol;

    const int ty = tid >> 4;           // 0..15
    const int tx = tid & 15;           // 0..15

    unsigned long long acc[8][4];
#pragma unroll
    for (int i = 0; i < 8; i++)
#pragma unroll
        for (int j = 0; j < 4; j++) acc[i][j] = 0ULL;

    float4 av = *(const float4*)(Ag);
    float4 bv = *(const float4*)(Wg);

    for (int kt = 0; kt < D_; kt += 8) {
        As[lcol+0][lrow] = av.x;
        As[lcol+1][lrow] = av.y;
        As[lcol+2][lrow] = av.z;
        As[lcol+3][lrow] = av.w;
        Bs[lcol+0][lrow] = bv.x;
        Bs[lcol+1][lrow] = bv.y;
        Bs[lcol+2][lrow] = bv.z;
        Bs[lcol+3][lrow] = bv.w;
        __syncthreads();

        if (kt + 8 < D_) {                       // prefetch next tile
            av = *(const float4*)(Ag + kt + 8);
            bv = *(const float4*)(Wg + kt + 8);
        }

#pragma unroll
        for (int k = 0; k < 8; k++) {
            float4 a0 = *(const float4*)&As[k][ty*4];
            float4 a1 = *(const float4*)&As[k][64 + ty*4];
            ulonglong2 b0 = *(const ulonglong2*)&Bs[k][tx*4];
            ulonglong2 b1 = *(const ulonglong2*)&Bs[k][64 + tx*4];
            float a[8] = {a0.x, a0.y, a0.z, a0.w, a1.x, a1.y, a1.z, a1.w};
            unsigned long long bb[4] = {b0.x, b0.y, b1.x, b1.y};
#pragma unroll
            for (int i = 0; i < 8; i++) {
                unsigned long long ad = pk2(a[i], a[i]);
#pragma unroll
                for (int j = 0; j < 4; j++)
                    acc[i][j] = ffma2(ad, bb[j], acc[i][j]);
            }
        }
        __syncthreads();
    }

#pragma unroll
    for (int i = 0; i < 8; i++) {
        int m = by*128 + ((i < 4) ? (ty*4 + i) : (64 + ty*4 + i - 4));
#pragma unroll
        for (int j = 0; j < 4; j++) {
            int n = bx*128 + ((j < 2) ? (tx*4 + j*2) : (64 + tx*4 + (j-2)*2));
            float2 v = upk2(acc[i][j]);
            float v0 = v.x + bias[n];
            float v1 = v.y + bias[n+1];
            if (mode == 0) {
                C[(size_t)m*D_ + n]     = v0;
                C[(size_t)m*D_ + n + 1] = v1;
            } else {
                // q/k/v scatter: [ (b*H+h) ][ s ][ d ]
                size_t base = ((size_t)((m >> 11)*H_ + (n >> 6)))*(size_t)(S_*DK)
                            + (size_t)(m & (S_-1))*DK;
                C[base + (n & 63)]       = v0;
                C[base + ((n+1) & 63)]   = v1;
            }
        }
    }
}

// ---------------- Flash attention, fp32, EPS-replace mask ------------------
#define BQ   64
#define CH   64
#define SPAD 68
#define ATTN_SMEM (4 * BQ * SPAD * (int)sizeof(float))   // 69632 B

union F4 { float4 v; float a[4]; };

__global__ __launch_bounds__(256, 2)
void attn_kernel(const float* __restrict__ Qm, const float* __restrict__ Km,
                 const float* __restrict__ Vm, const int* __restrict__ mask,
                 float* __restrict__ ctx)
{
    extern __shared__ __align__(16) float smbuf[];
    float (*Qs)[SPAD] = (float(*)[SPAD])(smbuf);
    float (*Ks)[SPAD] = (float(*)[SPAD])(smbuf + 1*BQ*SPAD);
    float (*Vs)[SPAD] = (float(*)[SPAD])(smbuf + 2*BQ*SPAD);
    float (*Ps)[SPAD] = (float(*)[SPAD])(smbuf + 3*BQ*SPAD);

    const int tid   = threadIdx.x;
    const int bh    = blockIdx.y;         // b*16 + h
    const int b     = bh >> 4;
    const int h     = bh & 15;
    const int qbase = blockIdx.x * BQ;

    const int ty = tid >> 4;              // 0..15 -> query rows ty*4..+3
    const int tx = tid & 15;              // 0..15
    const int r0 = ty * 4;
    const int d0 = tx * 4;                // head-dim cols in PV phase

    // load + pre-scale Q tile (scale = 1/sqrt(64) = 0.125)
    const float* Qg = Qm + ((size_t)bh*S_ + qbase)*DK;
    for (int idx = tid; idx < BQ*16; idx += 256) {
        int row = idx >> 4;
        int c4  = (idx & 15) << 2;
        float4 v = *(const float4*)(Qg + row*DK + c4);
        v.x *= 0.125f; v.y *= 0.125f; v.z *= 0.125f; v.w *= 0.125f;
        *(float4*)&Qs[row][c4] = v;
    }

    unsigned long long o2[4][2];          // O pairs along head dim
    float mi[4], li[4];
#pragma unroll
    for (int i = 0; i < 4; i++) {
        o2[i][0] = 0ULL; o2[i][1] = 0ULL;
        mi[i] = -1e30f;  li[i] = 0.f;
    }

    for (int kb = 0; kb < S_; kb += CH) {
        // load K/V chunk (Q sync covered by this barrier on first iter)
        const float* Kg = Km + ((size_t)bh*S_ + kb)*DK;
        const float* Vg = Vm + ((size_t)bh*S_ + kb)*DK;
        for (int idx = tid; idx < CH*16; idx += 256) {
            int row = idx >> 4;
            int c4  = (idx & 15) << 2;
            *(float4*)&Ks[row][c4] = *(const float4*)(Kg + row*DK + c4);
            *(float4*)&Vs[row][c4] = *(const float4*)(Vg + row*DK + c4);
        }
        __syncthreads();

        // ---- S = Q K^T : f32x2 horizontal accumulation along dk ----
        // thread owns rows r0..r0+3 and key cols {tx, tx+16, tx+32, tx+48}
        unsigned long long s2[4][4];
#pragma unroll
        for (int i = 0; i < 4; i++)
#pragma unroll
            for (int j = 0; j < 4; j++) s2[i][j] = 0ULL;

#pragma unroll 4
        for (int d = 0; d < DK; d += 4) {
            ulonglong2 qf[4], kf[4];
#pragma unroll
            for (int i = 0; i < 4; i++)
                qf[i] = *(const ulonglong2*)&Qs[r0+i][d];
#pragma unroll
            for (int j = 0; j < 4; j++)
                kf[j] = *(const ulonglong2*)&Ks[tx + 16*j][d];
#pragma unroll
            for (int i = 0; i < 4; i++)
#pragma unroll
                for (int j = 0; j < 4; j++) {
                    s2[i][j] = ffma2(qf[i].x, kf[j].x, s2[i][j]);
                    s2[i][j] = ffma2(qf[i].y, kf[j].y, s2[i][j]);
                }
        }

        // ---- mask + online softmax (row group = one half-warp) ----
#pragma unroll
        for (int i = 0; i < 4; i++) {
            const int* mrow = mask + ((size_t)b*S_ + (size_t)(qbase + r0 + i))*S_
                                   + kb + tx;
            float sv[4];
#pragma unroll
            for (int j = 0; j < 4; j++) {
                float2 u = upk2(s2[i][j]);
                float ss = u.x + u.y;
                sv[j] = (mrow[16*j] != 0) ? ss : EPSV;
            }
            float cm = fmaxf(fmaxf(sv[0], sv[1]), fmaxf(sv[2], sv[3]));
            cm = fmaxf(cm, __shfl_xor_sync(0xffffffffu, cm, 8, 16));
            cm = fmaxf(cm, __shfl_xor_sync(0xffffffffu, cm, 4, 16));
            cm = fmaxf(cm, __shfl_xor_sync(0xffffffffu, cm, 2, 16));
            cm = fmaxf(cm, __shfl_xor_sync(0xffffffffu, cm, 1, 16));
            float mnew  = fmaxf(mi[i], cm);
            float alpha = __expf(mi[i] - mnew);
            float psum  = 0.f;
#pragma unroll
            for (int j = 0; j < 4; j++) {
                float p = __expf(sv[j] - mnew);
                Ps[r0+i][tx + 16*j] = p;
                psum += p;
            }
            psum += __shfl_xor_sync(0xffffffffu, psum, 8, 16);
            psum += __shfl_xor_sync(0xffffffffu, psum, 4, 16);
            psum += __shfl_xor_sync(0xffffffffu, psum, 2, 16);
            psum += __shfl_xor_sync(0xffffffffu, psum, 1, 16);
            li[i] = li[i]*alpha + psum;
            mi[i] = mnew;
            unsigned long long a2 = pk2(alpha, alpha);
            o2[i][0] = fmul2(a2, o2[i][0]);
            o2[i][1] = fmul2(a2, o2[i][1]);
        }
        // P rows are produced & consumed by the same half-warp only
        __syncwarp();

        // ---- O += P @ V : pairs along head dim, natural V layout ----
#pragma unroll 4
        for (int c = 0; c < CH; c += 4) {
            F4 pf[4];
#pragma unroll
            for (int i = 0; i < 4; i++)
                pf[i].v = *(const float4*)&Ps[r0+i][c];
#pragma unroll
            for (int cc = 0; cc < 4; cc++) {
                ulonglong2 vv = *(const ulonglong2*)&Vs[c+cc][d0];
#pragma unroll
                for (int i = 0; i < 4; i++) {
                    unsigned long long pd = pk2(pf[i].a[cc], pf[i].a[cc]);
                    o2[i][0] = ffma2(pd, vv.x, o2[i][0]);
                    o2[i][1] = ffma2(pd, vv.y, o2[i][1]);
                }
            }
        }
        __syncthreads();   // all reads of Ks/Vs/Ps done before next chunk
    }

    // ---- normalize and write ctx[b][s][h*64+d] ----
#pragma unroll
    for (int i = 0; i < 4; i++) {
        int gq = qbase + r0 + i;
        float inv = 1.0f / li[i];
        float2 oa = upk2(o2[i][0]);
        float2 ob = upk2(o2[i][1]);
        float* dst = ctx + ((size_t)b*S_ + gq)*D_ + h*DK + d0;
        dst[0] = oa.x * inv;
        dst[1] = oa.y * inv;
        dst[2] = ob.x * inv;
        dst[3] = ob.y * inv;
    }
}

// ---------------- launch ---------------------------------------------------
extern "C" void kernel_launch(void* const* d_in, const int* in_sizes, int n_in,
                              void* d_out, int out_size)
{
    const float* query = (const float*)d_in[0];
    const float* key_  = (const float*)d_in[1];
    const float* value = (const float*)d_in[2];
    const int*   mask  = (const int*)  d_in[3];
    const float* wq    = (const float*)d_in[4];
    const float* bq    = (const float*)d_in[5];
    const float* wk    = (const float*)d_in[6];
    const float* bk    = (const float*)d_in[7];
    const float* wv    = (const float*)d_in[8];
    const float* bv    = (const float*)d_in[9];
    const float* wo    = (const float*)d_in[10];
    const float* bo    = (const float*)d_in[11];
    float* out = (float*)d_out;

    float *qp, *kp, *vp, *cp;
    cudaGetSymbolAddress((void**)&qp, g_q);
    cudaGetSymbolAddress((void**)&kp, g_k);
    cudaGetSymbolAddress((void**)&vp, g_v);
    cudaGetSymbolAddress((void**)&cp, g_ctx);

    // >48KB dynamic smem for attention (idempotent; also set on the
    // non-captured correctness call, so capture-time behavior is safe)
    cudaFuncSetAttribute(attn_kernel,
                         cudaFuncAttributeMaxDynamicSharedMemorySize,
                         ATTN_SMEM);

    dim3 blk(256);
    dim3 gg(D_/128, MTOT/128);          // (8, 64)

    sgemm_nt<<<gg, blk>>>(query, wq, bq, qp, 1);
    sgemm_nt<<<gg, blk>>>(key_,  wk, bk, kp, 1);
    sgemm_nt<<<gg, blk>>>(value, wv, bv, vp, 1);

    attn_kernel<<<dim3(S_/BQ, B_*H_), blk, ATTN_SMEM>>>(qp, kp, vp, mask, cp);

    sgemm_nt<<<gg, blk>>>(cp, wo, bo, out, 0);
}